// round 3
// baseline (speedup 1.0000x reference)
#include <cuda_runtime.h>
#include <math.h>

#define B_   2
#define S_   2048
#define DIM_ 1024
#define H_   16
#define DH_  64

// ---------------- scratch (no allocations allowed) ----------------
__device__ float g_qkv [B_ * S_ * 3 * DIM_];   // [b*s][3*1024]
__device__ float g_q   [B_ * H_ * S_ * DH_];   // [b,h,s,d]
__device__ float g_k   [B_ * H_ * S_ * DH_];
__device__ float g_v   [B_ * H_ * S_ * DH_];
__device__ float g_attn[B_ * S_ * DIM_];       // [b,s,h*64+d]

// =====================================================================
// Kernel 1/4: SGEMM  C[M,N] = A[M,K] * B[N,K]^T   (both row-major, NT)
// 128x128 block tile, 256 threads, 8x8 per thread, TK=16
// =====================================================================
__global__ __launch_bounds__(256, 2)
void sgemm_nt(const float* __restrict__ A, const float* __restrict__ Bm,
              float* __restrict__ C, int M, int N, int K) {
    __shared__ float As[16][128];
    __shared__ float Bs[16][128];

    const int tid = threadIdx.x;
    const int tx  = tid & 15;       // 0..15 -> n micro
    const int ty  = tid >> 4;       // 0..15 -> m micro
    const int m0  = blockIdx.y * 128;
    const int n0  = blockIdx.x * 128;

    const int lrow = tid >> 1;          // 0..127
    const int lk   = (tid & 1) * 8;     // 0 or 8

    const float* Ap = A  + (size_t)(m0 + lrow) * K + lk;
    const float* Bp = Bm + (size_t)(n0 + lrow) * K + lk;

    float acc[8][8];
#pragma unroll
    for (int r = 0; r < 8; r++)
#pragma unroll
        for (int c = 0; c < 8; c++) acc[r][c] = 0.f;

    for (int k0 = 0; k0 < K; k0 += 16) {
        float4 a0 = *(const float4*)(Ap + k0);
        float4 a1 = *(const float4*)(Ap + k0 + 4);
        float4 b0 = *(const float4*)(Bp + k0);
        float4 b1 = *(const float4*)(Bp + k0 + 4);

        __syncthreads();
        As[lk+0][lrow] = a0.x; As[lk+1][lrow] = a0.y;
        As[lk+2][lrow] = a0.z; As[lk+3][lrow] = a0.w;
        As[lk+4][lrow] = a1.x; As[lk+5][lrow] = a1.y;
        As[lk+6][lrow] = a1.z; As[lk+7][lrow] = a1.w;
        Bs[lk+0][lrow] = b0.x; Bs[lk+1][lrow] = b0.y;
        Bs[lk+2][lrow] = b0.z; Bs[lk+3][lrow] = b0.w;
        Bs[lk+4][lrow] = b1.x; Bs[lk+5][lrow] = b1.y;
        Bs[lk+6][lrow] = b1.z; Bs[lk+7][lrow] = b1.w;
        __syncthreads();

#pragma unroll
        for (int kk = 0; kk < 16; kk++) {
            float a[8], b[8];
            *(float4*)&a[0] = *(const float4*)&As[kk][ty * 8];
            *(float4*)&a[4] = *(const float4*)&As[kk][ty * 8 + 4];
            *(float4*)&b[0] = *(const float4*)&Bs[kk][tx * 8];
            *(float4*)&b[4] = *(const float4*)&Bs[kk][tx * 8 + 4];
#pragma unroll
            for (int r = 0; r < 8; r++)
#pragma unroll
                for (int c = 0; c < 8; c++)
                    acc[r][c] = fmaf(a[r], b[c], acc[r][c]);
        }
    }

#pragma unroll
    for (int r = 0; r < 8; r++) {
        float* Cp = C + (size_t)(m0 + ty * 8 + r) * N + n0 + tx * 8;
        float4 v0 = make_float4(acc[r][0], acc[r][1], acc[r][2], acc[r][3]);
        float4 v1 = make_float4(acc[r][4], acc[r][5], acc[r][6], acc[r][7]);
        *(float4*)(Cp)     = v0;
        *(float4*)(Cp + 4) = v1;
    }
}

// =====================================================================
// Kernel 2: per-head RMSNorm (q,k) + RoPE (q,k) + transpose to [b,h,s,d]
// grid = B*S blocks, 512 threads (16 warps = H heads), lane d & d+32
// =====================================================================
__global__ __launch_bounds__(512)
void qkv_post(const float* __restrict__ qkv, const float* __restrict__ rope,
              const float* __restrict__ qw, const float* __restrict__ kw,
              float* __restrict__ Q, float* __restrict__ K, float* __restrict__ V) {
    const int row  = blockIdx.x;           // b*S + s
    const int h    = threadIdx.x >> 5;
    const int lane = threadIdx.x & 31;
    const int b = row / S_;
    const int s = row - b * S_;

    const float* base = qkv + (size_t)row * (3 * DIM_) + h * DH_;
    float q1 = base[lane],            q2 = base[lane + 32];
    float k1 = base[DIM_ + lane],     k2 = base[DIM_ + lane + 32];
    float v1 = base[2*DIM_ + lane],   v2 = base[2*DIM_ + lane + 32];

    float qs = q1*q1 + q2*q2;
    float ks = k1*k1 + k2*k2;
#pragma unroll
    for (int o = 16; o >= 1; o >>= 1) {
        qs += __shfl_xor_sync(0xffffffffu, qs, o);
        ks += __shfl_xor_sync(0xffffffffu, ks, o);
    }
    const float qn = rsqrtf(qs * (1.0f / DH_) + 1e-6f);
    const float kn = rsqrtf(ks * (1.0f / DH_) + 1e-6f);

    q1 *= qn * qw[lane]; q2 *= qn * qw[lane + 32];
    k1 *= kn * kw[lane]; k2 *= kn * kw[lane + 32];

    // RoPE: accurate sincos (robust even under --use_fast_math; args up to 2047 rad)
    const float f = rope[(size_t)s * DH_ + lane];
    double sn, cs;
    sincos((double)f, &sn, &cs);
    const float cf = (float)cs, sf = (float)sn;

    const float qo1 = q1 * cf - q2 * sf;
    const float qo2 = q2 * cf + q1 * sf;
    const float ko1 = k1 * cf - k2 * sf;
    const float ko2 = k2 * cf + k1 * sf;

    const size_t o = (((size_t)(b * H_ + h)) * S_ + s) * DH_ + lane;
    Q[o] = qo1; Q[o + 32] = qo2;
    K[o] = ko1; K[o + 32] = ko2;
    V[o] = v1;  V[o + 32] = v2;
}

// =====================================================================
// Kernel 3: causal flash attention, fp32, BM=BN=DH=64
// grid = (32 q-tiles, 32 b*h), 256 threads, 4x4 micro-tiles
// dynamic smem: Qs/Ks/Vs/Ps each [64][68] floats = 69632 B
// =====================================================================
#define FPAD 68

__global__ __launch_bounds__(256, 2)
void flash_attn(const float* __restrict__ Q, const float* __restrict__ K,
                const float* __restrict__ V, float* __restrict__ Out) {
    extern __shared__ float sm[];
    float* Qs = sm;                 // [d][i]
    float* Ks = sm + 64 * FPAD;     // [d][j]
    float* Vs = sm + 2 * 64 * FPAD; // [t][d]
    float* Ps = sm + 3 * 64 * FPAD; // [t][i]

    const int tid = threadIdx.x;
    const int tx  = tid & 15;   // j / d micro
    const int ty  = tid >> 4;   // i micro
    const int qt  = blockIdx.x;
    const int bh  = blockIdx.y;
    const int q0  = qt * 64;

    const float* Qg = Q + ((size_t)bh * S_ + q0) * DH_;
    const float* Kg = K + (size_t)bh * S_ * DH_;
    const float* Vg = V + (size_t)bh * S_ * DH_;

    const int li  = tid >> 2;        // 0..63 (row loaded)
    const int ld0 = (tid & 3) * 16;  // d chunk

    // load Q tile transposed, fold in softmax scale 1/sqrt(64)
    {
        const float* src = Qg + (size_t)li * DH_ + ld0;
#pragma unroll
        for (int c = 0; c < 4; c++) {
            float4 v = *(const float4*)(src + c * 4);
            Qs[(ld0 + c*4 + 0) * FPAD + li] = v.x * 0.125f;
            Qs[(ld0 + c*4 + 1) * FPAD + li] = v.y * 0.125f;
            Qs[(ld0 + c*4 + 2) * FPAD + li] = v.z * 0.125f;
            Qs[(ld0 + c*4 + 3) * FPAD + li] = v.w * 0.125f;
        }
    }

    float m_r[4], l_r[4], o[4][4];
#pragma unroll
    for (int r = 0; r < 4; r++) {
        m_r[r] = -1e30f; l_r[r] = 0.f;
#pragma unroll
        for (int c = 0; c < 4; c++) o[r][c] = 0.f;
    }

    for (int kt = 0; kt <= qt; kt++) {
        __syncthreads();   // previous tile's smem reads done
        {
            const float* ksrc = Kg + ((size_t)(kt * 64 + li)) * DH_ + ld0;
            const float* vsrc = Vg + ((size_t)(kt * 64 + li)) * DH_ + ld0;
#pragma unroll
            for (int c = 0; c < 4; c++) {
                float4 kv = *(const float4*)(ksrc + c * 4);
                Ks[(ld0 + c*4 + 0) * FPAD + li] = kv.x;
                Ks[(ld0 + c*4 + 1) * FPAD + li] = kv.y;
                Ks[(ld0 + c*4 + 2) * FPAD + li] = kv.z;
                Ks[(ld0 + c*4 + 3) * FPAD + li] = kv.w;
                *(float4*)&Vs[li * FPAD + ld0 + c * 4] = *(const float4*)(vsrc + c * 4);
            }
        }
        __syncthreads();

        // S = Q K^T
        float sacc[4][4];
#pragma unroll
        for (int r = 0; r < 4; r++)
#pragma unroll
            for (int c = 0; c < 4; c++) sacc[r][c] = 0.f;

#pragma unroll 16
        for (int d = 0; d < 64; d++) {
            float4 qv = *(const float4*)&Qs[d * FPAD + ty * 4];
            float4 kv = *(const float4*)&Ks[d * FPAD + tx * 4];
            float qa[4] = {qv.x, qv.y, qv.z, qv.w};
            float ka[4] = {kv.x, kv.y, kv.z, kv.w};
#pragma unroll
            for (int r = 0; r < 4; r++)
#pragma unroll
                for (int c = 0; c < 4; c++)
                    sacc[r][c] = fmaf(qa[r], ka[c], sacc[r][c]);
        }

        if (kt == qt) {   // diagonal tile: causal mask
#pragma unroll
            for (int r = 0; r < 4; r++)
#pragma unroll
                for (int c = 0; c < 4; c++)
                    if (tx * 4 + c > ty * 4 + r) sacc[r][c] = -1e30f;
        }

        // online softmax (row groups = 16 lanes sharing ty; xor 1..8 stays in group)
#pragma unroll
        for (int r = 0; r < 4; r++) {
            float mx = fmaxf(fmaxf(sacc[r][0], sacc[r][1]), fmaxf(sacc[r][2], sacc[r][3]));
            mx = fmaxf(mx, __shfl_xor_sync(0xffffffffu, mx, 1));
            mx = fmaxf(mx, __shfl_xor_sync(0xffffffffu, mx, 2));
            mx = fmaxf(mx, __shfl_xor_sync(0xffffffffu, mx, 4));
            mx = fmaxf(mx, __shfl_xor_sync(0xffffffffu, mx, 8));
            const float mnew  = fmaxf(m_r[r], mx);
            const float alpha = __expf(m_r[r] - mnew);
            float rs = 0.f;
#pragma unroll
            for (int c = 0; c < 4; c++) {
                float p = __expf(sacc[r][c] - mnew);
                sacc[r][c] = p;
                rs += p;
            }
            rs += __shfl_xor_sync(0xffffffffu, rs, 1);
            rs += __shfl_xor_sync(0xffffffffu, rs, 2);
            rs += __shfl_xor_sync(0xffffffffu, rs, 4);
            rs += __shfl_xor_sync(0xffffffffu, rs, 8);
            l_r[r] = l_r[r] * alpha + rs;
            m_r[r] = mnew;
#pragma unroll
            for (int c = 0; c < 4; c++) o[r][c] *= alpha;
        }

        // stash P transposed: Ps[t][i]
#pragma unroll
        for (int c = 0; c < 4; c++) {
            float4 pv = make_float4(sacc[0][c], sacc[1][c], sacc[2][c], sacc[3][c]);
            *(float4*)&Ps[(tx * 4 + c) * FPAD + ty * 4] = pv;
        }
        __syncthreads();

        // O += P V
#pragma unroll 16
        for (int t = 0; t < 64; t++) {
            float4 pv = *(const float4*)&Ps[t * FPAD + ty * 4];
            float4 vv = *(const float4*)&Vs[t * FPAD + tx * 4];
            float pa[4] = {pv.x, pv.y, pv.z, pv.w};
            float va[4] = {vv.x, vv.y, vv.z, vv.w};
#pragma unroll
            for (int r = 0; r < 4; r++)
#pragma unroll
                for (int c = 0; c < 4; c++)
                    o[r][c] = fmaf(pa[r], va[c], o[r][c]);
        }
    }

    // epilogue: O / l  ->  attn buffer [b, s, h*64 + d]
    const int b = bh >> 4;
    const int h = bh & 15;
#pragma unroll
    for (int r = 0; r < 4; r++) {
        const float inv = 1.0f / l_r[r];
        float4 v = make_float4(o[r][0] * inv, o[r][1] * inv, o[r][2] * inv, o[r][3] * inv);
        float* dst = Out + ((size_t)(b * S_ + q0 + ty * 4 + r)) * DIM_ + h * DH_ + tx * 4;
        *(float4*)dst = v;
    }
}

// =====================================================================
extern "C" void kernel_launch(void* const* d_in, const int* in_sizes, int n_in,
                              void* d_out, int out_size) {
    const float* x     = (const float*)d_in[0];
    // d_in[1] = mask: causal tril(-1e9) — implemented structurally
    const float* rope  = (const float*)d_in[2];
    const float* w_qkv = (const float*)d_in[3];
    const float* w_out = (const float*)d_in[4];
    const float* qw    = (const float*)d_in[5];
    const float* kw    = (const float*)d_in[6];
    float* out = (float*)d_out;

    // Pure lookups every call — no static state, deterministic, capture-legal.
    float *qkv_p, *q_p, *k_p, *v_p, *attn_p;
    cudaGetSymbolAddress((void**)&qkv_p,  g_qkv);
    cudaGetSymbolAddress((void**)&q_p,    g_q);
    cudaGetSymbolAddress((void**)&k_p,    g_k);
    cudaGetSymbolAddress((void**)&v_p,    g_v);
    cudaGetSymbolAddress((void**)&attn_p, g_attn);

    const int smem = 4 * 64 * FPAD * sizeof(float);   // 69632
    cudaFuncSetAttribute(flash_attn, cudaFuncAttributeMaxDynamicSharedMemorySize, smem);

    const int M = B_ * S_;        // 4096

    // 1) QKV projection: [4096,3072] = x[4096,1024] * w_qkv[3072,1024]^T
    sgemm_nt<<<dim3(3 * DIM_ / 128, M / 128), 256>>>(x, w_qkv, qkv_p, M, 3 * DIM_, DIM_);

    // 2) RMSNorm + RoPE + transpose
    qkv_post<<<M, 512>>>(qkv_p, rope, qw, kw, q_p, k_p, v_p);

    // 3) causal flash attention
    flash_attn<<<dim3(S_ / 64, B_ * H_), 256, smem>>>(q_p, k_p, v_p, attn_p);

    // 4) output projection: [4096,1024] = attn[4096,1024] * w_out[1024,1024]^T
    sgemm_nt<<<dim3(DIM_ / 128, M / 128), 256>>>(attn_p, w_out, out, M, DIM_, DIM_);
}

// round 5
// speedup vs baseline: 1.6068x; 1.6068x over previous
#include <cuda_runtime.h>
#include <math.h>
#include <stdint.h>

#define B_   2
#define S_   2048
#define DIM_ 1024
#define H_   16
#define DH_  64

// ---------------- scratch (no allocations allowed) ----------------
__device__ float g_qkv [B_ * S_ * 3 * DIM_];   // [b*s][3*1024]
__device__ float g_q   [B_ * H_ * S_ * DH_];   // [b,h,s,d]
__device__ float g_k   [B_ * H_ * S_ * DH_];
__device__ float g_v   [B_ * H_ * S_ * DH_];
__device__ float g_attn[B_ * S_ * DIM_];       // [b,s,h*64+d]

__device__ __forceinline__ uint32_t f2tf32(float f) {
    uint32_t r;
    asm("cvt.rna.tf32.f32 %0, %1;" : "=r"(r) : "f"(f));
    return r;
}

// =====================================================================
// Kernel 1: TF32 tensor-core GEMM  C[M,N] = A[M,K] * B[N,K]^T  (NT)
// 128x128 block tile, 256 threads (8 warps), warp tile 64x32,
// mma.sync.m16n8k8.tf32, BK=32, smem [row][k] pitch 36 (conflict-free)
// =====================================================================
#define GK 32
#define GPITCH 36

__global__ __launch_bounds__(256, 2)
void gemm_tf32_nt(const float* __restrict__ A, const float* __restrict__ Bm,
                  float* __restrict__ C, int M, int N, int K) {
    __shared__ uint32_t As[128][GPITCH];
    __shared__ uint32_t Bs[128][GPITCH];

    const int tid  = threadIdx.x;
    const int wid  = tid >> 5;
    const int lane = tid & 31;
    const int wm   = wid & 1;        // 0..1  -> m offset wm*64
    const int wn   = wid >> 1;       // 0..3  -> n offset wn*32
    const int m0   = blockIdx.y * 128;
    const int n0   = blockIdx.x * 128;

    const int lr = tid >> 3;         // 0..31 base row (rows lr, lr+32, lr+64, lr+96)
    const int lc = (tid & 7) * 4;    // k quad start

    const float* Ap = A  + (size_t)(m0 + lr) * K + lc;
    const float* Bp = Bm + (size_t)(n0 + lr) * K + lc;

    float c[4][4][4];
#pragma unroll
    for (int im = 0; im < 4; im++)
#pragma unroll
        for (int jn = 0; jn < 4; jn++)
#pragma unroll
            for (int e = 0; e < 4; e++) c[im][jn][e] = 0.f;

    const int gr = lane >> 2;        // 0..7
    const int gc = lane & 3;         // 0..3

    for (int k0 = 0; k0 < K; k0 += GK) {
        // prefetch gmem (coalesced float4 along K)
        float4 av[4], bv[4];
#pragma unroll
        for (int t = 0; t < 4; t++) {
            av[t] = *(const float4*)(Ap + k0 + (size_t)(t * 32) * K);
            bv[t] = *(const float4*)(Bp + k0 + (size_t)(t * 32) * K);
        }
        __syncthreads();
#pragma unroll
        for (int t = 0; t < 4; t++) {
            uint32_t* ad = &As[lr + t * 32][lc];
            ad[0] = f2tf32(av[t].x); ad[1] = f2tf32(av[t].y);
            ad[2] = f2tf32(av[t].z); ad[3] = f2tf32(av[t].w);
            uint32_t* bd = &Bs[lr + t * 32][lc];
            bd[0] = f2tf32(bv[t].x); bd[1] = f2tf32(bv[t].y);
            bd[2] = f2tf32(bv[t].z); bd[3] = f2tf32(bv[t].w);
        }
        __syncthreads();

#pragma unroll
        for (int ks = 0; ks < 4; ks++) {
            const int k = ks * 8;
            uint32_t af[4][4], bf[4][2];
#pragma unroll
            for (int im = 0; im < 4; im++) {
                const int mr = wm * 64 + im * 16 + gr;
                af[im][0] = As[mr    ][k + gc];
                af[im][1] = As[mr + 8][k + gc];
                af[im][2] = As[mr    ][k + gc + 4];
                af[im][3] = As[mr + 8][k + gc + 4];
            }
#pragma unroll
            for (int jn = 0; jn < 4; jn++) {
                const int nr = wn * 32 + jn * 8 + gr;
                bf[jn][0] = Bs[nr][k + gc];
                bf[jn][1] = Bs[nr][k + gc + 4];
            }
#pragma unroll
            for (int im = 0; im < 4; im++)
#pragma unroll
                for (int jn = 0; jn < 4; jn++) {
                    asm volatile(
                        "mma.sync.aligned.m16n8k8.row.col.f32.tf32.tf32.f32 "
                        "{%0,%1,%2,%3}, {%4,%5,%6,%7}, {%8,%9}, {%0,%1,%2,%3};\n"
                        : "+f"(c[im][jn][0]), "+f"(c[im][jn][1]),
                          "+f"(c[im][jn][2]), "+f"(c[im][jn][3])
                        : "r"(af[im][0]), "r"(af[im][1]), "r"(af[im][2]), "r"(af[im][3]),
                          "r"(bf[jn][0]), "r"(bf[jn][1]));
                }
        }
    }

    // epilogue
#pragma unroll
    for (int im = 0; im < 4; im++) {
        const int row = m0 + wm * 64 + im * 16 + gr;
#pragma unroll
        for (int jn = 0; jn < 4; jn++) {
            const int col = n0 + wn * 32 + jn * 8 + gc * 2;
            float* p0 = C + (size_t)row * N + col;
            float* p1 = C + (size_t)(row + 8) * N + col;
            p0[0] = c[im][jn][0]; p0[1] = c[im][jn][1];
            p1[0] = c[im][jn][2]; p1[1] = c[im][jn][3];
        }
    }
}

// =====================================================================
// Kernel 2: per-head RMSNorm (q,k) + RoPE (q,k) + transpose to [b,h,s,d]
// =====================================================================
__global__ __launch_bounds__(512)
void qkv_post(const float* __restrict__ qkv, const float* __restrict__ rope,
              const float* __restrict__ qw, const float* __restrict__ kw,
              float* __restrict__ Q, float* __restrict__ K, float* __restrict__ V) {
    const int row  = blockIdx.x;           // b*S + s
    const int h    = threadIdx.x >> 5;
    const int lane = threadIdx.x & 31;
    const int b = row / S_;
    const int s = row - b * S_;

    const float* base = qkv + (size_t)row * (3 * DIM_) + h * DH_;
    float q1 = base[lane],            q2 = base[lane + 32];
    float k1 = base[DIM_ + lane],     k2 = base[DIM_ + lane + 32];
    float v1 = base[2*DIM_ + lane],   v2 = base[2*DIM_ + lane + 32];

    float qs = q1*q1 + q2*q2;
    float ks = k1*k1 + k2*k2;
#pragma unroll
    for (int o = 16; o >= 1; o >>= 1) {
        qs += __shfl_xor_sync(0xffffffffu, qs, o);
        ks += __shfl_xor_sync(0xffffffffu, ks, o);
    }
    const float qn = rsqrtf(qs * (1.0f / DH_) + 1e-6f);
    const float kn = rsqrtf(ks * (1.0f / DH_) + 1e-6f);

    q1 *= qn * qw[lane]; q2 *= qn * qw[lane + 32];
    k1 *= kn * kw[lane]; k2 *= kn * kw[lane + 32];

    const float f = rope[(size_t)s * DH_ + lane];
    double sn, cs;
    sincos((double)f, &sn, &cs);
    const float cf = (float)cs, sf = (float)sn;

    const float qo1 = q1 * cf - q2 * sf;
    const float qo2 = q2 * cf + q1 * sf;
    const float ko1 = k1 * cf - k2 * sf;
    const float ko2 = k2 * cf + k1 * sf;

    const size_t o = (((size_t)(b * H_ + h)) * S_ + s) * DH_ + lane;
    Q[o] = qo1; Q[o + 32] = qo2;
    K[o] = ko1; K[o + 32] = ko2;
    V[o] = v1;  V[o + 32] = v2;
}

// =====================================================================
// Kernel 3: causal flash attention, fp32, BM=BN=DH=64
// =====================================================================
#define FPAD 68

__global__ __launch_bounds__(256, 2)
void flash_attn(const float* __restrict__ Q, const float* __restrict__ K,
                const float* __restrict__ V, float* __restrict__ Out) {
    extern __shared__ float sm[];
    float* Qs = sm;                 // [d][i]
    float* Ks = sm + 64 * FPAD;     // [d][j]
    float* Vs = sm + 2 * 64 * FPAD; // [t][d]
    float* Ps = sm + 3 * 64 * FPAD; // [t][i]

    const int tid = threadIdx.x;
    const int tx  = tid & 15;
    const int ty  = tid >> 4;
    const int qt  = blockIdx.x;
    const int bh  = blockIdx.y;
    const int q0  = qt * 64;

    const float* Qg = Q + ((size_t)bh * S_ + q0) * DH_;
    const float* Kg = K + (size_t)bh * S_ * DH_;
    const float* Vg = V + (size_t)bh * S_ * DH_;

    const int li  = tid >> 2;
    const int ld0 = (tid & 3) * 16;

    {
        const float* src = Qg + (size_t)li * DH_ + ld0;
#pragma unroll
        for (int c = 0; c < 4; c++) {
            float4 v = *(const float4*)(src + c * 4);
            Qs[(ld0 + c*4 + 0) * FPAD + li] = v.x * 0.125f;
            Qs[(ld0 + c*4 + 1) * FPAD + li] = v.y * 0.125f;
            Qs[(ld0 + c*4 + 2) * FPAD + li] = v.z * 0.125f;
            Qs[(ld0 + c*4 + 3) * FPAD + li] = v.w * 0.125f;
        }
    }

    float m_r[4], l_r[4], o[4][4];
#pragma unroll
    for (int r = 0; r < 4; r++) {
        m_r[r] = -1e30f; l_r[r] = 0.f;
#pragma unroll
        for (int c = 0; c < 4; c++) o[r][c] = 0.f;
    }

    for (int kt = 0; kt <= qt; kt++) {
        __syncthreads();
        {
            const float* ksrc = Kg + ((size_t)(kt * 64 + li)) * DH_ + ld0;
            const float* vsrc = Vg + ((size_t)(kt * 64 + li)) * DH_ + ld0;
#pragma unroll
            for (int c = 0; c < 4; c++) {
                float4 kv = *(const float4*)(ksrc + c * 4);
                Ks[(ld0 + c*4 + 0) * FPAD + li] = kv.x;
                Ks[(ld0 + c*4 + 1) * FPAD + li] = kv.y;
                Ks[(ld0 + c*4 + 2) * FPAD + li] = kv.z;
                Ks[(ld0 + c*4 + 3) * FPAD + li] = kv.w;
                *(float4*)&Vs[li * FPAD + ld0 + c * 4] = *(const float4*)(vsrc + c * 4);
            }
        }
        __syncthreads();

        float sacc[4][4];
#pragma unroll
        for (int r = 0; r < 4; r++)
#pragma unroll
            for (int c = 0; c < 4; c++) sacc[r][c] = 0.f;

#pragma unroll 16
        for (int d = 0; d < 64; d++) {
            float4 qv = *(const float4*)&Qs[d * FPAD + ty * 4];
            float4 kv = *(const float4*)&Ks[d * FPAD + tx * 4];
            float qa[4] = {qv.x, qv.y, qv.z, qv.w};
            float ka[4] = {kv.x, kv.y, kv.z, kv.w};
#pragma unroll
            for (int r = 0; r < 4; r++)
#pragma unroll
                for (int c = 0; c < 4; c++)
                    sacc[r][c] = fmaf(qa[r], ka[c], sacc[r][c]);
        }

        if (kt == qt) {
#pragma unroll
            for (int r = 0; r < 4; r++)
#pragma unroll
                for (int c = 0; c < 4; c++)
                    if (tx * 4 + c > ty * 4 + r) sacc[r][c] = -1e30f;
        }

#pragma unroll
        for (int r = 0; r < 4; r++) {
            float mx = fmaxf(fmaxf(sacc[r][0], sacc[r][1]), fmaxf(sacc[r][2], sacc[r][3]));
            mx = fmaxf(mx, __shfl_xor_sync(0xffffffffu, mx, 1));
            mx = fmaxf(mx, __shfl_xor_sync(0xffffffffu, mx, 2));
            mx = fmaxf(mx, __shfl_xor_sync(0xffffffffu, mx, 4));
            mx = fmaxf(mx, __shfl_xor_sync(0xffffffffu, mx, 8));
            const float mnew  = fmaxf(m_r[r], mx);
            const float alpha = __expf(m_r[r] - mnew);
            float rs = 0.f;
#pragma unroll
            for (int c = 0; c < 4; c++) {
                float p = __expf(sacc[r][c] - mnew);
                sacc[r][c] = p;
                rs += p;
            }
            rs += __shfl_xor_sync(0xffffffffu, rs, 1);
            rs += __shfl_xor_sync(0xffffffffu, rs, 2);
            rs += __shfl_xor_sync(0xffffffffu, rs, 4);
            rs += __shfl_xor_sync(0xffffffffu, rs, 8);
            l_r[r] = l_r[r] * alpha + rs;
            m_r[r] = mnew;
#pragma unroll
            for (int c = 0; c < 4; c++) o[r][c] *= alpha;
        }

#pragma unroll
        for (int c = 0; c < 4; c++) {
            float4 pv = make_float4(sacc[0][c], sacc[1][c], sacc[2][c], sacc[3][c]);
            *(float4*)&Ps[(tx * 4 + c) * FPAD + ty * 4] = pv;
        }
        __syncthreads();

#pragma unroll 16
        for (int t = 0; t < 64; t++) {
            float4 pv = *(const float4*)&Ps[t * FPAD + ty * 4];
            float4 vv = *(const float4*)&Vs[t * FPAD + tx * 4];
            float pa[4] = {pv.x, pv.y, pv.z, pv.w};
            float va[4] = {vv.x, vv.y, vv.z, vv.w};
#pragma unroll
            for (int r = 0; r < 4; r++)
#pragma unroll
                for (int c = 0; c < 4; c++)
                    o[r][c] = fmaf(pa[r], va[c], o[r][c]);
        }
    }

    const int b = bh >> 4;
    const int h = bh & 15;
#pragma unroll
    for (int r = 0; r < 4; r++) {
        const float inv = 1.0f / l_r[r];
        float4 v = make_float4(o[r][0] * inv, o[r][1] * inv, o[r][2] * inv, o[r][3] * inv);
        float* dst = Out + ((size_t)(b * S_ + q0 + ty * 4 + r)) * DIM_ + h * DH_ + tx * 4;
        *(float4*)dst = v;
    }
}

// =====================================================================
extern "C" void kernel_launch(void* const* d_in, const int* in_sizes, int n_in,
                              void* d_out, int out_size) {
    const float* x     = (const float*)d_in[0];
    // d_in[1] = mask: causal tril(-1e9) — implemented structurally
    const float* rope  = (const float*)d_in[2];
    const float* w_qkv = (const float*)d_in[3];
    const float* w_out = (const float*)d_in[4];
    const float* qw    = (const float*)d_in[5];
    const float* kw    = (const float*)d_in[6];
    float* out = (float*)d_out;

    float *qkv_p, *q_p, *k_p, *v_p, *attn_p;
    cudaGetSymbolAddress((void**)&qkv_p,  g_qkv);
    cudaGetSymbolAddress((void**)&q_p,    g_q);
    cudaGetSymbolAddress((void**)&k_p,    g_k);
    cudaGetSymbolAddress((void**)&v_p,    g_v);
    cudaGetSymbolAddress((void**)&attn_p, g_attn);

    const int smem = 4 * 64 * FPAD * sizeof(float);   // 69632
    cudaFuncSetAttribute(flash_attn, cudaFuncAttributeMaxDynamicSharedMemorySize, smem);

    const int M = B_ * S_;        // 4096

    // 1) QKV projection (tf32 tensor cores)
    gemm_tf32_nt<<<dim3(3 * DIM_ / 128, M / 128), 256>>>(x, w_qkv, qkv_p, M, 3 * DIM_, DIM_);

    // 2) RMSNorm + RoPE + transpose
    qkv_post<<<M, 512>>>(qkv_p, rope, qw, kw, q_p, k_p, v_p);

    // 3) causal flash attention
    flash_attn<<<dim3(S_ / 64, B_ * H_), 256, smem>>>(q_p, k_p, v_p, attn_p);

    // 4) output projection (tf32 tensor cores)
    gemm_tf32_nt<<<dim3(DIM_ / 128, M / 128), 256>>>(attn_p, w_out, out, M, DIM_, DIM_);
}

// round 7
// speedup vs baseline: 2.2227x; 1.3833x over previous
#include <cuda_runtime.h>
#include <math.h>
#include <stdint.h>

#define B_   2
#define S_   2048
#define DIM_ 1024
#define H_   16
#define DH_  64

// ---------------- scratch (no allocations allowed) ----------------
__device__ float g_qkv [B_ * S_ * 3 * DIM_];   // [b*s][3*1024]
__device__ float g_q   [B_ * H_ * S_ * DH_];   // [b,h,s,d]
__device__ float g_k   [B_ * H_ * S_ * DH_];
__device__ float g_v   [B_ * H_ * S_ * DH_];
__device__ float g_attn[B_ * S_ * DIM_];       // [b,s,h*64+d]

__device__ __forceinline__ uint32_t f2tf32(float f) {
    uint32_t r;
    asm("cvt.rna.tf32.f32 %0, %1;" : "=r"(r) : "f"(f));
    return r;
}

__device__ __forceinline__ void mma_tf32(float* c, const uint32_t* a, const uint32_t* b) {
    asm volatile(
        "mma.sync.aligned.m16n8k8.row.col.f32.tf32.tf32.f32 "
        "{%0,%1,%2,%3}, {%4,%5,%6,%7}, {%8,%9}, {%0,%1,%2,%3};\n"
        : "+f"(c[0]), "+f"(c[1]), "+f"(c[2]), "+f"(c[3])
        : "r"(a[0]), "r"(a[1]), "r"(a[2]), "r"(a[3]), "r"(b[0]), "r"(b[1]));
}

// =====================================================================
// Kernel 1: TF32 tensor-core GEMM  C[M,N] = A[M,K] * B[N,K]^T  (NT)
// =====================================================================
#define GK 32
#define GPITCH 36

__global__ __launch_bounds__(256, 2)
void gemm_tf32_nt(const float* __restrict__ A, const float* __restrict__ Bm,
                  float* __restrict__ C, int M, int N, int K) {
    __shared__ uint32_t As[128][GPITCH];
    __shared__ uint32_t Bs[128][GPITCH];

    const int tid  = threadIdx.x;
    const int wid  = tid >> 5;
    const int lane = tid & 31;
    const int wm   = wid & 1;
    const int wn   = wid >> 1;
    const int m0   = blockIdx.y * 128;
    const int n0   = blockIdx.x * 128;

    const int lr = tid >> 3;
    const int lc = (tid & 7) * 4;

    const float* Ap = A  + (size_t)(m0 + lr) * K + lc;
    const float* Bp = Bm + (size_t)(n0 + lr) * K + lc;

    float c[4][4][4];
#pragma unroll
    for (int im = 0; im < 4; im++)
#pragma unroll
        for (int jn = 0; jn < 4; jn++)
#pragma unroll
            for (int e = 0; e < 4; e++) c[im][jn][e] = 0.f;

    const int gr = lane >> 2;
    const int gc = lane & 3;

    for (int k0 = 0; k0 < K; k0 += GK) {
        float4 av[4], bv[4];
#pragma unroll
        for (int t = 0; t < 4; t++) {
            av[t] = *(const float4*)(Ap + k0 + (size_t)(t * 32) * K);
            bv[t] = *(const float4*)(Bp + k0 + (size_t)(t * 32) * K);
        }
        __syncthreads();
#pragma unroll
        for (int t = 0; t < 4; t++) {
            uint32_t* ad = &As[lr + t * 32][lc];
            ad[0] = f2tf32(av[t].x); ad[1] = f2tf32(av[t].y);
            ad[2] = f2tf32(av[t].z); ad[3] = f2tf32(av[t].w);
            uint32_t* bd = &Bs[lr + t * 32][lc];
            bd[0] = f2tf32(bv[t].x); bd[1] = f2tf32(bv[t].y);
            bd[2] = f2tf32(bv[t].z); bd[3] = f2tf32(bv[t].w);
        }
        __syncthreads();

#pragma unroll
        for (int ks = 0; ks < 4; ks++) {
            const int k = ks * 8;
            uint32_t af[4][4], bf[4][2];
#pragma unroll
            for (int im = 0; im < 4; im++) {
                const int mr = wm * 64 + im * 16 + gr;
                af[im][0] = As[mr    ][k + gc];
                af[im][1] = As[mr + 8][k + gc];
                af[im][2] = As[mr    ][k + gc + 4];
                af[im][3] = As[mr + 8][k + gc + 4];
            }
#pragma unroll
            for (int jn = 0; jn < 4; jn++) {
                const int nr = wn * 32 + jn * 8 + gr;
                bf[jn][0] = Bs[nr][k + gc];
                bf[jn][1] = Bs[nr][k + gc + 4];
            }
#pragma unroll
            for (int im = 0; im < 4; im++)
#pragma unroll
                for (int jn = 0; jn < 4; jn++)
                    mma_tf32(c[im][jn], af[im], bf[jn]);
        }
    }

#pragma unroll
    for (int im = 0; im < 4; im++) {
        const int row = m0 + wm * 64 + im * 16 + gr;
#pragma unroll
        for (int jn = 0; jn < 4; jn++) {
            const int col = n0 + wn * 32 + jn * 8 + gc * 2;
            float* p0 = C + (size_t)row * N + col;
            float* p1 = C + (size_t)(row + 8) * N + col;
            p0[0] = c[im][jn][0]; p0[1] = c[im][jn][1];
            p1[0] = c[im][jn][2]; p1[1] = c[im][jn][3];
        }
    }
}

// =====================================================================
// Kernel 2: per-head RMSNorm (q,k) + RoPE (q,k) + transpose to [b,h,s,d]
// =====================================================================
__global__ __launch_bounds__(512)
void qkv_post(const float* __restrict__ qkv, const float* __restrict__ rope,
              const float* __restrict__ qw, const float* __restrict__ kw,
              float* __restrict__ Q, float* __restrict__ K, float* __restrict__ V) {
    const int row  = blockIdx.x;
    const int h    = threadIdx.x >> 5;
    const int lane = threadIdx.x & 31;
    const int b = row / S_;
    const int s = row - b * S_;

    const float* base = qkv + (size_t)row * (3 * DIM_) + h * DH_;
    float q1 = base[lane],            q2 = base[lane + 32];
    float k1 = base[DIM_ + lane],     k2 = base[DIM_ + lane + 32];
    float v1 = base[2*DIM_ + lane],   v2 = base[2*DIM_ + lane + 32];

    float qs = q1*q1 + q2*q2;
    float ks = k1*k1 + k2*k2;
#pragma unroll
    for (int o = 16; o >= 1; o >>= 1) {
        qs += __shfl_xor_sync(0xffffffffu, qs, o);
        ks += __shfl_xor_sync(0xffffffffu, ks, o);
    }
    const float qn = rsqrtf(qs * (1.0f / DH_) + 1e-6f);
    const float kn = rsqrtf(ks * (1.0f / DH_) + 1e-6f);

    q1 *= qn * qw[lane]; q2 *= qn * qw[lane + 32];
    k1 *= kn * kw[lane]; k2 *= kn * kw[lane + 32];

    const float f = rope[(size_t)s * DH_ + lane];
    double sn, cs;
    sincos((double)f, &sn, &cs);
    const float cf = (float)cs, sf = (float)sn;

    const float qo1 = q1 * cf - q2 * sf;
    const float qo2 = q2 * cf + q1 * sf;
    const float ko1 = k1 * cf - k2 * sf;
    const float ko2 = k2 * cf + k1 * sf;

    const size_t o = (((size_t)(b * H_ + h)) * S_ + s) * DH_ + lane;
    Q[o] = qo1; Q[o + 32] = qo2;
    K[o] = ko1; K[o + 32] = ko2;
    V[o] = v1;  V[o + 32] = v2;
}

// =====================================================================
// Kernel 3: tensor-core causal flash attention (tf32 MMA)
// BM=BN=DH=64, 128 threads (4 warps), warp = 16 q rows.
// smem: Ks[64][68] tf32, Vs[64][72] tf32, Qs[64][68] tf32 (reused as P)
// =====================================================================
#define KP 68
#define VP 72

__global__ __launch_bounds__(128)
void flash_attn_tc(const float* __restrict__ Q, const float* __restrict__ K,
                   const float* __restrict__ V, float* __restrict__ Out) {
    extern __shared__ uint32_t smx[];
    uint32_t* Ks = smx;                       // [64][KP]
    uint32_t* Vs = smx + 64 * KP;             // [64][VP]
    uint32_t* Qs = smx + 64 * KP + 64 * VP;   // [64][KP], later P per-warp

    const int tid  = threadIdx.x;
    const int w    = tid >> 5;
    const int lane = tid & 31;
    const int gr   = lane >> 2;   // 0..7
    const int gc   = lane & 3;    // 0..3
    const int qt   = blockIdx.x;
    const int bh   = blockIdx.y;
    const int q0   = qt * 64;

    const float* Qg = Q + ((size_t)bh * S_ + q0) * DH_;
    const float* Kg = K + (size_t)bh * S_ * DH_;
    const float* Vg = V + (size_t)bh * S_ * DH_;

    const int lrow = tid >> 1;           // 0..63
    const int lcol = (tid & 1) * 32;     // 0 / 32

    // ---- load Q tile (scaled, tf32) to smem ----
    {
        const float* src = Qg + (size_t)lrow * DH_ + lcol;
        uint32_t* dst = Qs + lrow * KP + lcol;
#pragma unroll
        for (int i = 0; i < 8; i++) {
            float4 v = *(const float4*)(src + i * 4);
            dst[i*4+0] = f2tf32(v.x * 0.125f);
            dst[i*4+1] = f2tf32(v.y * 0.125f);
            dst[i*4+2] = f2tf32(v.z * 0.125f);
            dst[i*4+3] = f2tf32(v.w * 0.125f);
        }
    }
    __syncthreads();

    // ---- cache Q A-fragments in registers (whole KV loop) ----
    uint32_t qf[8][4];
    {
        const int m0r = (w * 16 + gr) * KP;
        const int m1r = (w * 16 + gr + 8) * KP;
#pragma unroll
        for (int ks = 0; ks < 8; ks++) {
            const int d0 = ks * 8 + gc;
            qf[ks][0] = Qs[m0r + d0];
            qf[ks][1] = Qs[m1r + d0];
            qf[ks][2] = Qs[m0r + d0 + 4];
            qf[ks][3] = Qs[m1r + d0 + 4];
        }
    }
    // per-warp P region reuses this warp's own 16 Q rows (no cross-warp hazard)
    uint32_t* Ps = Qs + w * 16 * KP;

    float of[8][4];
#pragma unroll
    for (int j = 0; j < 8; j++)
#pragma unroll
        for (int e = 0; e < 4; e++) of[j][e] = 0.f;
    float m0 = -1e30f, m1 = -1e30f, l0 = 0.f, l1 = 0.f;

    for (int kt = 0; kt <= qt; kt++) {
        __syncthreads();   // all warps done with previous K/V
        {
            const float* ksrc = Kg + ((size_t)(kt * 64 + lrow)) * DH_ + lcol;
            const float* vsrc = Vg + ((size_t)(kt * 64 + lrow)) * DH_ + lcol;
            uint32_t* kd = Ks + lrow * KP + lcol;
            uint32_t* vd = Vs + lrow * VP + lcol;
#pragma unroll
            for (int i = 0; i < 8; i++) {
                float4 kv = *(const float4*)(ksrc + i * 4);
                float4 vv = *(const float4*)(vsrc + i * 4);
                kd[i*4+0] = f2tf32(kv.x); kd[i*4+1] = f2tf32(kv.y);
                kd[i*4+2] = f2tf32(kv.z); kd[i*4+3] = f2tf32(kv.w);
                vd[i*4+0] = f2tf32(vv.x); vd[i*4+1] = f2tf32(vv.y);
                vd[i*4+2] = f2tf32(vv.z); vd[i*4+3] = f2tf32(vv.w);
            }
        }
        __syncthreads();

        // ---- S = Q K^T  (per warp: 16 x 64) ----
        float sacc[8][4];
#pragma unroll
        for (int j = 0; j < 8; j++)
#pragma unroll
            for (int e = 0; e < 4; e++) sacc[j][e] = 0.f;

#pragma unroll
        for (int ks = 0; ks < 8; ks++) {
            const int d0 = ks * 8 + gc;
            uint32_t kb[8][2];
#pragma unroll
            for (int j = 0; j < 8; j++) {
                const int tr = (j * 8 + gr) * KP;
                kb[j][0] = Ks[tr + d0];
                kb[j][1] = Ks[tr + d0 + 4];
            }
#pragma unroll
            for (int j = 0; j < 8; j++) mma_tf32(sacc[j], qf[ks], kb[j]);
        }

        // ---- causal mask on diagonal tile ----
        if (kt == qt) {
            const int r0 = w * 16 + gr, r1 = r0 + 8;
#pragma unroll
            for (int j = 0; j < 8; j++) {
                const int c0 = j * 8 + 2 * gc;
                if (c0     > r0) sacc[j][0] = -1e30f;
                if (c0 + 1 > r0) sacc[j][1] = -1e30f;
                if (c0     > r1) sacc[j][2] = -1e30f;
                if (c0 + 1 > r1) sacc[j][3] = -1e30f;
            }
        }

        // ---- online softmax (rows gr and gr+8; reduce over gc lanes) ----
        float mx0 = -1e30f, mx1 = -1e30f;
#pragma unroll
        for (int j = 0; j < 8; j++) {
            mx0 = fmaxf(mx0, fmaxf(sacc[j][0], sacc[j][1]));
            mx1 = fmaxf(mx1, fmaxf(sacc[j][2], sacc[j][3]));
        }
        mx0 = fmaxf(mx0, __shfl_xor_sync(0xffffffffu, mx0, 1));
        mx0 = fmaxf(mx0, __shfl_xor_sync(0xffffffffu, mx0, 2));
        mx1 = fmaxf(mx1, __shfl_xor_sync(0xffffffffu, mx1, 1));
        mx1 = fmaxf(mx1, __shfl_xor_sync(0xffffffffu, mx1, 2));

        const float mn0 = fmaxf(m0, mx0);
        const float mn1 = fmaxf(m1, mx1);
        const float a0 = __expf(m0 - mn0);
        const float a1 = __expf(m1 - mn1);
        m0 = mn0; m1 = mn1;

        float rs0 = 0.f, rs1 = 0.f;
#pragma unroll
        for (int j = 0; j < 8; j++) {
            sacc[j][0] = __expf(sacc[j][0] - mn0);
            sacc[j][1] = __expf(sacc[j][1] - mn0);
            sacc[j][2] = __expf(sacc[j][2] - mn1);
            sacc[j][3] = __expf(sacc[j][3] - mn1);
            rs0 += sacc[j][0] + sacc[j][1];
            rs1 += sacc[j][2] + sacc[j][3];
        }
        rs0 += __shfl_xor_sync(0xffffffffu, rs0, 1);
        rs0 += __shfl_xor_sync(0xffffffffu, rs0, 2);
        rs1 += __shfl_xor_sync(0xffffffffu, rs1, 1);
        rs1 += __shfl_xor_sync(0xffffffffu, rs1, 2);
        l0 = l0 * a0 + rs0;
        l1 = l1 * a1 + rs1;

#pragma unroll
        for (int j = 0; j < 8; j++) {
            of[j][0] *= a0; of[j][1] *= a0;
            of[j][2] *= a1; of[j][3] *= a1;
        }

        // ---- stash P (tf32) in per-warp smem slice [16][KP] ----
#pragma unroll
        for (int j = 0; j < 8; j++) {
            const int c0 = j * 8 + 2 * gc;
            Ps[gr * KP + c0]           = f2tf32(sacc[j][0]);
            Ps[gr * KP + c0 + 1]       = f2tf32(sacc[j][1]);
            Ps[(gr + 8) * KP + c0]     = f2tf32(sacc[j][2]);
            Ps[(gr + 8) * KP + c0 + 1] = f2tf32(sacc[j][3]);
        }
        __syncwarp();

        // ---- O += P V  (contract over t) ----
#pragma unroll
        for (int ks = 0; ks < 8; ks++) {
            const int t0 = ks * 8;
            uint32_t pf[4];
            pf[0] = Ps[gr * KP + t0 + gc];
            pf[1] = Ps[(gr + 8) * KP + t0 + gc];
            pf[2] = Ps[gr * KP + t0 + gc + 4];
            pf[3] = Ps[(gr + 8) * KP + t0 + gc + 4];
            uint32_t vb[8][2];
#pragma unroll
            for (int j = 0; j < 8; j++) {
                vb[j][0] = Vs[(t0 + gc) * VP + j * 8 + gr];
                vb[j][1] = Vs[(t0 + gc + 4) * VP + j * 8 + gr];
            }
#pragma unroll
            for (int j = 0; j < 8; j++) mma_tf32(of[j], pf, vb[j]);
        }
        __syncwarp();
    }

    // ---- epilogue: O/l -> attn buffer [b, s, h*64+d] ----
    const int b = bh >> 4;
    const int h = bh & 15;
    const float inv0 = 1.0f / l0;
    const float inv1 = 1.0f / l1;
    const int s0 = q0 + w * 16 + gr;
    const int s1 = s0 + 8;
#pragma unroll
    for (int j = 0; j < 8; j++) {
        const int col = h * DH_ + j * 8 + 2 * gc;
        float* p0 = Out + ((size_t)(b * S_ + s0)) * DIM_ + col;
        float* p1 = Out + ((size_t)(b * S_ + s1)) * DIM_ + col;
        *(float2*)p0 = make_float2(of[j][0] * inv0, of[j][1] * inv0);
        *(float2*)p1 = make_float2(of[j][2] * inv1, of[j][3] * inv1);
    }
}

// =====================================================================
extern "C" void kernel_launch(void* const* d_in, const int* in_sizes, int n_in,
                              void* d_out, int out_size) {
    const float* x     = (const float*)d_in[0];
    // d_in[1] = mask: causal tril(-1e9) — implemented structurally
    const float* rope  = (const float*)d_in[2];
    const float* w_qkv = (const float*)d_in[3];
    const float* w_out = (const float*)d_in[4];
    const float* qw    = (const float*)d_in[5];
    const float* kw    = (const float*)d_in[6];
    float* out = (float*)d_out;

    float *qkv_p, *q_p, *k_p, *v_p, *attn_p;
    cudaGetSymbolAddress((void**)&qkv_p,  g_qkv);
    cudaGetSymbolAddress((void**)&q_p,    g_q);
    cudaGetSymbolAddress((void**)&k_p,    g_k);
    cudaGetSymbolAddress((void**)&v_p,    g_v);
    cudaGetSymbolAddress((void**)&attn_p, g_attn);

    const int smem = (64 * KP + 64 * VP + 64 * KP) * sizeof(uint32_t);  // 53248
    cudaFuncSetAttribute(flash_attn_tc, cudaFuncAttributeMaxDynamicSharedMemorySize, smem);

    const int M = B_ * S_;        // 4096

    // 1) QKV projection (tf32 tensor cores)
    gemm_tf32_nt<<<dim3(3 * DIM_ / 128, M / 128), 256>>>(x, w_qkv, qkv_p, M, 3 * DIM_, DIM_);

    // 2) RMSNorm + RoPE + transpose
    qkv_post<<<M, 512>>>(qkv_p, rope, qw, kw, q_p, k_p, v_p);

    // 3) causal flash attention (tf32 tensor cores)
    flash_attn_tc<<<dim3(S_ / 64, B_ * H_), 128, smem>>>(q_p, k_p, v_p, attn_p);

    // 4) output projection (tf32 tensor cores)
    gemm_tf32_nt<<<dim3(DIM_ / 128, M / 128), 256>>>(attn_p, w_out, out, M, DIM_, DIM_);
}

// round 8
// speedup vs baseline: 2.3395x; 1.0526x over previous
#include <cuda_runtime.h>
#include <math.h>
#include <stdint.h>

#define B_   2
#define S_   2048
#define DIM_ 1024
#define H_   16
#define DH_  64

// ---------------- scratch (no allocations allowed) ----------------
__device__ float g_qkv [B_ * S_ * 3 * DIM_];   // [b*s][3*1024]
__device__ float g_q   [B_ * H_ * S_ * DH_];   // [b,h,s,d]
__device__ float g_k   [B_ * H_ * S_ * DH_];
__device__ float g_v   [B_ * H_ * S_ * DH_];
__device__ float g_attn[B_ * S_ * DIM_];       // [b,s,h*64+d]

__device__ __forceinline__ uint32_t f2tf32(float f) {
    uint32_t r;
    asm("cvt.rna.tf32.f32 %0, %1;" : "=r"(r) : "f"(f));
    return r;
}

__device__ __forceinline__ void mma_tf32(float* c, const uint32_t* a, const uint32_t* b) {
    asm volatile(
        "mma.sync.aligned.m16n8k8.row.col.f32.tf32.tf32.f32 "
        "{%0,%1,%2,%3}, {%4,%5,%6,%7}, {%8,%9}, {%0,%1,%2,%3};\n"
        : "+f"(c[0]), "+f"(c[1]), "+f"(c[2]), "+f"(c[3])
        : "r"(a[0]), "r"(a[1]), "r"(a[2]), "r"(a[3]), "r"(b[0]), "r"(b[1]));
}

// =====================================================================
// Kernel 1: TF32 GEMM  C[M,N] = A[M,K] * B[N,K]^T  (NT)
// 128x128 tile, 256 thr, double-buffered smem + reg prefetch, 1 sync/iter
// =====================================================================
#define GK 32
#define GPITCH 36
#define GASZ (128 * GPITCH)          // one buffer, words

__global__ __launch_bounds__(256, 2)
void gemm_tf32_nt(const float* __restrict__ A, const float* __restrict__ Bm,
                  float* __restrict__ C, int M, int N, int K) {
    extern __shared__ uint32_t gsm[];
    uint32_t* Asb = gsm;             // [2][128][GPITCH]
    uint32_t* Bsb = gsm + 2 * GASZ;  // [2][128][GPITCH]

    const int tid  = threadIdx.x;
    const int wid  = tid >> 5;
    const int lane = tid & 31;
    const int wm   = wid & 1;
    const int wn   = wid >> 1;
    const int m0   = blockIdx.y * 128;
    const int n0   = blockIdx.x * 128;

    const int lr = tid >> 3;
    const int lc = (tid & 7) * 4;

    const float* Ap = A  + (size_t)(m0 + lr) * K + lc;
    const float* Bp = Bm + (size_t)(n0 + lr) * K + lc;

    float c[4][4][4];
#pragma unroll
    for (int im = 0; im < 4; im++)
#pragma unroll
        for (int jn = 0; jn < 4; jn++)
#pragma unroll
            for (int e = 0; e < 4; e++) c[im][jn][e] = 0.f;

    const int gr = lane >> 2;
    const int gc = lane & 3;

    float4 av[4], bv[4];
    // ---- preload tile k0=0 into buffer 0 ----
#pragma unroll
    for (int t = 0; t < 4; t++) {
        av[t] = *(const float4*)(Ap + (size_t)(t * 32) * K);
        bv[t] = *(const float4*)(Bp + (size_t)(t * 32) * K);
    }
#pragma unroll
    for (int t = 0; t < 4; t++) {
        uint32_t* ad = Asb + (lr + t * 32) * GPITCH + lc;
        ad[0] = f2tf32(av[t].x); ad[1] = f2tf32(av[t].y);
        ad[2] = f2tf32(av[t].z); ad[3] = f2tf32(av[t].w);
        uint32_t* bd = Bsb + (lr + t * 32) * GPITCH + lc;
        bd[0] = f2tf32(bv[t].x); bd[1] = f2tf32(bv[t].y);
        bd[2] = f2tf32(bv[t].z); bd[3] = f2tf32(bv[t].w);
    }
    __syncthreads();

    int buf = 0;
    for (int k0 = 0; k0 < K; k0 += GK) {
        const bool next = (k0 + GK) < K;
        // issue next tile's loads (overlap with MMAs below)
        if (next) {
#pragma unroll
            for (int t = 0; t < 4; t++) {
                av[t] = *(const float4*)(Ap + k0 + GK + (size_t)(t * 32) * K);
                bv[t] = *(const float4*)(Bp + k0 + GK + (size_t)(t * 32) * K);
            }
        }

        const uint32_t* As = Asb + buf * GASZ;
        const uint32_t* Bs = Bsb + buf * GASZ;
#pragma unroll
        for (int ks = 0; ks < 4; ks++) {
            const int k = ks * 8;
            uint32_t af[4][4], bf[4][2];
#pragma unroll
            for (int im = 0; im < 4; im++) {
                const int mr = wm * 64 + im * 16 + gr;
                af[im][0] = As[mr * GPITCH + k + gc];
                af[im][1] = As[(mr + 8) * GPITCH + k + gc];
                af[im][2] = As[mr * GPITCH + k + gc + 4];
                af[im][3] = As[(mr + 8) * GPITCH + k + gc + 4];
            }
#pragma unroll
            for (int jn = 0; jn < 4; jn++) {
                const int nr = wn * 32 + jn * 8 + gr;
                bf[jn][0] = Bs[nr * GPITCH + k + gc];
                bf[jn][1] = Bs[nr * GPITCH + k + gc + 4];
            }
#pragma unroll
            for (int im = 0; im < 4; im++)
#pragma unroll
                for (int jn = 0; jn < 4; jn++)
                    mma_tf32(c[im][jn], af[im], bf[jn]);
        }

        if (next) {
            uint32_t* Asn = Asb + (buf ^ 1) * GASZ;
            uint32_t* Bsn = Bsb + (buf ^ 1) * GASZ;
#pragma unroll
            for (int t = 0; t < 4; t++) {
                uint32_t* ad = Asn + (lr + t * 32) * GPITCH + lc;
                ad[0] = f2tf32(av[t].x); ad[1] = f2tf32(av[t].y);
                ad[2] = f2tf32(av[t].z); ad[3] = f2tf32(av[t].w);
                uint32_t* bd = Bsn + (lr + t * 32) * GPITCH + lc;
                bd[0] = f2tf32(bv[t].x); bd[1] = f2tf32(bv[t].y);
                bd[2] = f2tf32(bv[t].z); bd[3] = f2tf32(bv[t].w);
            }
            __syncthreads();
            buf ^= 1;
        }
    }

#pragma unroll
    for (int im = 0; im < 4; im++) {
        const int row = m0 + wm * 64 + im * 16 + gr;
#pragma unroll
        for (int jn = 0; jn < 4; jn++) {
            const int col = n0 + wn * 32 + jn * 8 + gc * 2;
            float* p0 = C + (size_t)row * N + col;
            float* p1 = C + (size_t)(row + 8) * N + col;
            p0[0] = c[im][jn][0]; p0[1] = c[im][jn][1];
            p1[0] = c[im][jn][2]; p1[1] = c[im][jn][3];
        }
    }
}

// =====================================================================
// Kernel 2: per-head RMSNorm (q,k) + RoPE (q,k) + transpose to [b,h,s,d]
// =====================================================================
__global__ __launch_bounds__(512)
void qkv_post(const float* __restrict__ qkv, const float* __restrict__ rope,
              const float* __restrict__ qw, const float* __restrict__ kw,
              float* __restrict__ Q, float* __restrict__ K, float* __restrict__ V) {
    const int row  = blockIdx.x;
    const int h    = threadIdx.x >> 5;
    const int lane = threadIdx.x & 31;
    const int b = row / S_;
    const int s = row - b * S_;

    const float* base = qkv + (size_t)row * (3 * DIM_) + h * DH_;
    float q1 = base[lane],            q2 = base[lane + 32];
    float k1 = base[DIM_ + lane],     k2 = base[DIM_ + lane + 32];
    float v1 = base[2*DIM_ + lane],   v2 = base[2*DIM_ + lane + 32];

    float qs = q1*q1 + q2*q2;
    float ks = k1*k1 + k2*k2;
#pragma unroll
    for (int o = 16; o >= 1; o >>= 1) {
        qs += __shfl_xor_sync(0xffffffffu, qs, o);
        ks += __shfl_xor_sync(0xffffffffu, ks, o);
    }
    const float qn = rsqrtf(qs * (1.0f / DH_) + 1e-6f);
    const float kn = rsqrtf(ks * (1.0f / DH_) + 1e-6f);

    q1 *= qn * qw[lane]; q2 *= qn * qw[lane + 32];
    k1 *= kn * kw[lane]; k2 *= kn * kw[lane + 32];

    const float f = rope[(size_t)s * DH_ + lane];
    double sn, cs;
    sincos((double)f, &sn, &cs);
    const float cf = (float)cs, sf = (float)sn;

    const float qo1 = q1 * cf - q2 * sf;
    const float qo2 = q2 * cf + q1 * sf;
    const float ko1 = k1 * cf - k2 * sf;
    const float ko2 = k2 * cf + k1 * sf;

    const size_t o = (((size_t)(b * H_ + h)) * S_ + s) * DH_ + lane;
    Q[o] = qo1; Q[o + 32] = qo2;
    K[o] = ko1; K[o + 32] = ko2;
    V[o] = v1;  V[o + 32] = v2;
}

// =====================================================================
// Kernel 3: tensor-core causal flash attention (tf32 MMA)
// BM=BN=DH=64, 128 threads (4 warps), warp = 16 q rows.
// Double-buffered K/V smem; next tile's LDGs overlap the PV MMAs.
// smem: Ks[2][64][68], Vs[2][64][72], Qs[64][68] (Qs reused as P)
// =====================================================================
#define KP 68
#define VP 72
#define KSZ (64 * KP)
#define VSZ (64 * VP)

__global__ __launch_bounds__(128)
void flash_attn_tc(const float* __restrict__ Q, const float* __restrict__ K,
                   const float* __restrict__ V, float* __restrict__ Out) {
    extern __shared__ uint32_t smx[];
    uint32_t* Ksb = smx;                       // [2][64*KP]
    uint32_t* Vsb = smx + 2 * KSZ;             // [2][64*VP]
    uint32_t* Qs  = smx + 2 * KSZ + 2 * VSZ;   // [64*KP], later P per-warp

    const int tid  = threadIdx.x;
    const int w    = tid >> 5;
    const int lane = tid & 31;
    const int gr   = lane >> 2;   // 0..7
    const int gc   = lane & 3;    // 0..3
    const int qt   = blockIdx.x;
    const int bh   = blockIdx.y;
    const int q0   = qt * 64;

    const float* Qg = Q + ((size_t)bh * S_ + q0) * DH_;
    const float* Kg = K + (size_t)bh * S_ * DH_;
    const float* Vg = V + (size_t)bh * S_ * DH_;

    const int lrow = tid >> 1;           // 0..63
    const int lcol = (tid & 1) * 32;     // 0 / 32

    // ---- load Q tile (scaled, tf32) + K/V tile 0 into buffer 0 ----
    {
        const float* src = Qg + (size_t)lrow * DH_ + lcol;
        uint32_t* dst = Qs + lrow * KP + lcol;
#pragma unroll
        for (int i = 0; i < 8; i++) {
            float4 v = *(const float4*)(src + i * 4);
            dst[i*4+0] = f2tf32(v.x * 0.125f);
            dst[i*4+1] = f2tf32(v.y * 0.125f);
            dst[i*4+2] = f2tf32(v.z * 0.125f);
            dst[i*4+3] = f2tf32(v.w * 0.125f);
        }
        const float* ksrc = Kg + (size_t)lrow * DH_ + lcol;
        const float* vsrc = Vg + (size_t)lrow * DH_ + lcol;
        uint32_t* kd = Ksb + lrow * KP + lcol;
        uint32_t* vd = Vsb + lrow * VP + lcol;
#pragma unroll
        for (int i = 0; i < 8; i++) {
            float4 kv = *(const float4*)(ksrc + i * 4);
            float4 vv = *(const float4*)(vsrc + i * 4);
            kd[i*4+0] = f2tf32(kv.x); kd[i*4+1] = f2tf32(kv.y);
            kd[i*4+2] = f2tf32(kv.z); kd[i*4+3] = f2tf32(kv.w);
            vd[i*4+0] = f2tf32(vv.x); vd[i*4+1] = f2tf32(vv.y);
            vd[i*4+2] = f2tf32(vv.z); vd[i*4+3] = f2tf32(vv.w);
        }
    }
    __syncthreads();

    // ---- cache Q A-fragments in registers (whole KV loop) ----
    uint32_t qf[8][4];
    {
        const int m0r = (w * 16 + gr) * KP;
        const int m1r = (w * 16 + gr + 8) * KP;
#pragma unroll
        for (int ks = 0; ks < 8; ks++) {
            const int d0 = ks * 8 + gc;
            qf[ks][0] = Qs[m0r + d0];
            qf[ks][1] = Qs[m1r + d0];
            qf[ks][2] = Qs[m0r + d0 + 4];
            qf[ks][3] = Qs[m1r + d0 + 4];
        }
    }
    // per-warp P region reuses this warp's own 16 Q rows
    uint32_t* Ps = Qs + w * 16 * KP;

    float of[8][4];
#pragma unroll
    for (int j = 0; j < 8; j++)
#pragma unroll
        for (int e = 0; e < 4; e++) of[j][e] = 0.f;
    float m0 = -1e30f, m1 = -1e30f, l0 = 0.f, l1 = 0.f;

    int buf = 0;
    for (int kt = 0; kt <= qt; kt++) {
        const uint32_t* Ks = Ksb + buf * KSZ;
        const uint32_t* Vs = Vsb + buf * VSZ;

        // ---- S = Q K^T  (per warp: 16 x 64) ----
        float sacc[8][4];
#pragma unroll
        for (int j = 0; j < 8; j++)
#pragma unroll
            for (int e = 0; e < 4; e++) sacc[j][e] = 0.f;

#pragma unroll
        for (int ks = 0; ks < 8; ks++) {
            const int d0 = ks * 8 + gc;
            uint32_t kb[8][2];
#pragma unroll
            for (int j = 0; j < 8; j++) {
                const int tr = (j * 8 + gr) * KP;
                kb[j][0] = Ks[tr + d0];
                kb[j][1] = Ks[tr + d0 + 4];
            }
#pragma unroll
            for (int j = 0; j < 8; j++) mma_tf32(sacc[j], qf[ks], kb[j]);
        }

        // ---- causal mask on diagonal tile ----
        if (kt == qt) {
            const int r0 = w * 16 + gr, r1 = r0 + 8;
#pragma unroll
            for (int j = 0; j < 8; j++) {
                const int c0 = j * 8 + 2 * gc;
                if (c0     > r0) sacc[j][0] = -1e30f;
                if (c0 + 1 > r0) sacc[j][1] = -1e30f;
                if (c0     > r1) sacc[j][2] = -1e30f;
                if (c0 + 1 > r1) sacc[j][3] = -1e30f;
            }
        }

        // ---- online softmax ----
        float mx0 = -1e30f, mx1 = -1e30f;
#pragma unroll
        for (int j = 0; j < 8; j++) {
            mx0 = fmaxf(mx0, fmaxf(sacc[j][0], sacc[j][1]));
            mx1 = fmaxf(mx1, fmaxf(sacc[j][2], sacc[j][3]));
        }
        mx0 = fmaxf(mx0, __shfl_xor_sync(0xffffffffu, mx0, 1));
        mx0 = fmaxf(mx0, __shfl_xor_sync(0xffffffffu, mx0, 2));
        mx1 = fmaxf(mx1, __shfl_xor_sync(0xffffffffu, mx1, 1));
        mx1 = fmaxf(mx1, __shfl_xor_sync(0xffffffffu, mx1, 2));

        const float mn0 = fmaxf(m0, mx0);
        const float mn1 = fmaxf(m1, mx1);
        const float a0 = __expf(m0 - mn0);
        const float a1 = __expf(m1 - mn1);
        m0 = mn0; m1 = mn1;

        float rs0 = 0.f, rs1 = 0.f;
#pragma unroll
        for (int j = 0; j < 8; j++) {
            sacc[j][0] = __expf(sacc[j][0] - mn0);
            sacc[j][1] = __expf(sacc[j][1] - mn0);
            sacc[j][2] = __expf(sacc[j][2] - mn1);
            sacc[j][3] = __expf(sacc[j][3] - mn1);
            rs0 += sacc[j][0] + sacc[j][1];
            rs1 += sacc[j][2] + sacc[j][3];
        }
        rs0 += __shfl_xor_sync(0xffffffffu, rs0, 1);
        rs0 += __shfl_xor_sync(0xffffffffu, rs0, 2);
        rs1 += __shfl_xor_sync(0xffffffffu, rs1, 1);
        rs1 += __shfl_xor_sync(0xffffffffu, rs1, 2);
        l0 = l0 * a0 + rs0;
        l1 = l1 * a1 + rs1;

#pragma unroll
        for (int j = 0; j < 8; j++) {
            of[j][0] *= a0; of[j][1] *= a0;
            of[j][2] *= a1; of[j][3] *= a1;
        }

        // ---- stash P (tf32) in per-warp smem slice ----
#pragma unroll
        for (int j = 0; j < 8; j++) {
            const int c0 = j * 8 + 2 * gc;
            Ps[gr * KP + c0]           = f2tf32(sacc[j][0]);
            Ps[gr * KP + c0 + 1]       = f2tf32(sacc[j][1]);
            Ps[(gr + 8) * KP + c0]     = f2tf32(sacc[j][2]);
            Ps[(gr + 8) * KP + c0 + 1] = f2tf32(sacc[j][3]);
        }
        __syncwarp();

        // ---- issue next K/V tile's loads (overlap with PV MMAs) ----
        const bool next = kt < qt;
        float4 kr[8], vr[8];
        if (next) {
            const float* ksrc = Kg + ((size_t)((kt + 1) * 64 + lrow)) * DH_ + lcol;
            const float* vsrc = Vg + ((size_t)((kt + 1) * 64 + lrow)) * DH_ + lcol;
#pragma unroll
            for (int i = 0; i < 8; i++) {
                kr[i] = *(const float4*)(ksrc + i * 4);
                vr[i] = *(const float4*)(vsrc + i * 4);
            }
        }

        // ---- O += P V ----
#pragma unroll
        for (int ks = 0; ks < 8; ks++) {
            const int t0 = ks * 8;
            uint32_t pf[4];
            pf[0] = Ps[gr * KP + t0 + gc];
            pf[1] = Ps[(gr + 8) * KP + t0 + gc];
            pf[2] = Ps[gr * KP + t0 + gc + 4];
            pf[3] = Ps[(gr + 8) * KP + t0 + gc + 4];
            uint32_t vb[8][2];
#pragma unroll
            for (int j = 0; j < 8; j++) {
                vb[j][0] = Vs[(t0 + gc) * VP + j * 8 + gr];
                vb[j][1] = Vs[(t0 + gc + 4) * VP + j * 8 + gr];
            }
#pragma unroll
            for (int j = 0; j < 8; j++) mma_tf32(of[j], pf, vb[j]);
        }
        __syncwarp();

        // ---- store prefetched tile into other buffer, single sync ----
        if (next) {
            uint32_t* kd = Ksb + (buf ^ 1) * KSZ + lrow * KP + lcol;
            uint32_t* vd = Vsb + (buf ^ 1) * VSZ + lrow * VP + lcol;
#pragma unroll
            for (int i = 0; i < 8; i++) {
                kd[i*4+0] = f2tf32(kr[i].x); kd[i*4+1] = f2tf32(kr[i].y);
                kd[i*4+2] = f2tf32(kr[i].z); kd[i*4+3] = f2tf32(kr[i].w);
                vd[i*4+0] = f2tf32(vr[i].x); vd[i*4+1] = f2tf32(vr[i].y);
                vd[i*4+2] = f2tf32(vr[i].z); vd[i*4+3] = f2tf32(vr[i].w);
            }
            __syncthreads();
            buf ^= 1;
        }
    }

    // ---- epilogue: O/l -> attn buffer [b, s, h*64+d] ----
    const int b = bh >> 4;
    const int h = bh & 15;
    const float inv0 = 1.0f / l0;
    const float inv1 = 1.0f / l1;
    const int s0 = q0 + w * 16 + gr;
    const int s1 = s0 + 8;
#pragma unroll
    for (int j = 0; j < 8; j++) {
        const int col = h * DH_ + j * 8 + 2 * gc;
        float* p0 = Out + ((size_t)(b * S_ + s0)) * DIM_ + col;
        float* p1 = Out + ((size_t)(b * S_ + s1)) * DIM_ + col;
        *(float2*)p0 = make_float2(of[j][0] * inv0, of[j][1] * inv0);
        *(float2*)p1 = make_float2(of[j][2] * inv1, of[j][3] * inv1);
    }
}

// =====================================================================
extern "C" void kernel_launch(void* const* d_in, const int* in_sizes, int n_in,
                              void* d_out, int out_size) {
    const float* x     = (const float*)d_in[0];
    // d_in[1] = mask: causal tril(-1e9) — implemented structurally
    const float* rope  = (const float*)d_in[2];
    const float* w_qkv = (const float*)d_in[3];
    const float* w_out = (const float*)d_in[4];
    const float* qw    = (const float*)d_in[5];
    const float* kw    = (const float*)d_in[6];
    float* out = (float*)d_out;

    float *qkv_p, *q_p, *k_p, *v_p, *attn_p;
    cudaGetSymbolAddress((void**)&qkv_p,  g_qkv);
    cudaGetSymbolAddress((void**)&q_p,    g_q);
    cudaGetSymbolAddress((void**)&k_p,    g_k);
    cudaGetSymbolAddress((void**)&v_p,    g_v);
    cudaGetSymbolAddress((void**)&attn_p, g_attn);

    const int gemm_smem = 4 * GASZ * sizeof(uint32_t);                    // 73728
    const int attn_smem = (2 * KSZ + 2 * VSZ + KSZ) * sizeof(uint32_t);   // 89088
    cudaFuncSetAttribute(gemm_tf32_nt, cudaFuncAttributeMaxDynamicSharedMemorySize, gemm_smem);
    cudaFuncSetAttribute(flash_attn_tc, cudaFuncAttributeMaxDynamicSharedMemorySize, attn_smem);

    const int M = B_ * S_;        // 4096

    // 1) QKV projection (tf32 tensor cores, pipelined)
    gemm_tf32_nt<<<dim3(3 * DIM_ / 128, M / 128), 256, gemm_smem>>>(x, w_qkv, qkv_p, M, 3 * DIM_, DIM_);

    // 2) RMSNorm + RoPE + transpose
    qkv_post<<<M, 512>>>(qkv_p, rope, qw, kw, q_p, k_p, v_p);

    // 3) causal flash attention (tf32 tensor cores, pipelined)
    flash_attn_tc<<<dim3(S_ / 64, B_ * H_), 128, attn_smem>>>(q_p, k_p, v_p, attn_p);

    // 4) output projection (tf32 tensor cores, pipelined)
    gemm_tf32_nt<<<dim3(DIM_ / 128, M / 128), 256, gemm_smem>>>(attn_p, w_out, out, M, DIM_, DIM_);
}

// round 10
// speedup vs baseline: 3.1701x; 1.3550x over previous
#include <cuda_runtime.h>
#include <math.h>
#include <stdint.h>

#define B_   2
#define S_   2048
#define DIM_ 1024
#define H_   16
#define DH_  64

// ---------------- scratch (no allocations allowed) ----------------
__device__ float g_qkv [B_ * S_ * 3 * DIM_];   // [b*s][3*1024]
__device__ float g_q   [B_ * H_ * S_ * DH_];   // [b,h,s,d]
__device__ float g_k   [B_ * H_ * S_ * DH_];
__device__ float g_v   [B_ * H_ * S_ * DH_];
__device__ float g_attn[B_ * S_ * DIM_];       // [b,s,h*64+d]
__device__ float g_rlut[S_ * DH_];             // [s][cos32|sin32]

__device__ __forceinline__ uint32_t f2tf32(float f) {
    uint32_t r;
    asm("cvt.rna.tf32.f32 %0, %1;" : "=r"(r) : "f"(f));
    return r;
}

__device__ __forceinline__ void mma_tf32(float* c, const uint32_t* a, const uint32_t* b) {
    asm volatile(
        "mma.sync.aligned.m16n8k8.row.col.f32.tf32.tf32.f32 "
        "{%0,%1,%2,%3}, {%4,%5,%6,%7}, {%8,%9}, {%0,%1,%2,%3};\n"
        : "+f"(c[0]), "+f"(c[1]), "+f"(c[2]), "+f"(c[3])
        : "r"(a[0]), "r"(a[1]), "r"(a[2]), "r"(a[3]), "r"(b[0]), "r"(b[1]));
}

// =====================================================================
// Kernel 0: RoPE cos/sin LUT (65K accurate sincos once, not 2M in qkv_post)
// =====================================================================
__global__ void rope_lut(const float* __restrict__ rope, float* __restrict__ lut) {
    const int s = blockIdx.x;
    const int d = threadIdx.x;          // 0..31
    const float f = rope[(size_t)s * DH_ + d];
    double sn, cs;
    sincos((double)f, &sn, &cs);
    lut[s * DH_ + d]      = (float)cs;
    lut[s * DH_ + 32 + d] = (float)sn;
}

// =====================================================================
// Kernel 1: TF32 GEMM  C[M,N] = A[M,K] * B[N,K]^T  (NT)
// 128x128 tile, 256 thr, double-buffered smem + reg prefetch, 1 sync/iter
// =====================================================================
#define GK 32
#define GPITCH 36
#define GASZ (128 * GPITCH)

__global__ __launch_bounds__(256, 2)
void gemm_tf32_nt(const float* __restrict__ A, const float* __restrict__ Bm,
                  float* __restrict__ C, int M, int N, int K) {
    extern __shared__ uint32_t gsm[];
    uint32_t* Asb = gsm;
    uint32_t* Bsb = gsm + 2 * GASZ;

    const int tid  = threadIdx.x;
    const int wid  = tid >> 5;
    const int lane = tid & 31;
    const int wm   = wid & 1;
    const int wn   = wid >> 1;
    const int m0   = blockIdx.y * 128;
    const int n0   = blockIdx.x * 128;

    const int lr = tid >> 3;
    const int lc = (tid & 7) * 4;

    const float* Ap = A  + (size_t)(m0 + lr) * K + lc;
    const float* Bp = Bm + (size_t)(n0 + lr) * K + lc;

    float c[4][4][4];
#pragma unroll
    for (int im = 0; im < 4; im++)
#pragma unroll
        for (int jn = 0; jn < 4; jn++)
#pragma unroll
            for (int e = 0; e < 4; e++) c[im][jn][e] = 0.f;

    const int gr = lane >> 2;
    const int gc = lane & 3;

    float4 av[4], bv[4];
#pragma unroll
    for (int t = 0; t < 4; t++) {
        av[t] = *(const float4*)(Ap + (size_t)(t * 32) * K);
        bv[t] = *(const float4*)(Bp + (size_t)(t * 32) * K);
    }
#pragma unroll
    for (int t = 0; t < 4; t++) {
        uint32_t* ad = Asb + (lr + t * 32) * GPITCH + lc;
        ad[0] = f2tf32(av[t].x); ad[1] = f2tf32(av[t].y);
        ad[2] = f2tf32(av[t].z); ad[3] = f2tf32(av[t].w);
        uint32_t* bd = Bsb + (lr + t * 32) * GPITCH + lc;
        bd[0] = f2tf32(bv[t].x); bd[1] = f2tf32(bv[t].y);
        bd[2] = f2tf32(bv[t].z); bd[3] = f2tf32(bv[t].w);
    }
    __syncthreads();

    int buf = 0;
    for (int k0 = 0; k0 < K; k0 += GK) {
        const bool next = (k0 + GK) < K;
        if (next) {
#pragma unroll
            for (int t = 0; t < 4; t++) {
                av[t] = *(const float4*)(Ap + k0 + GK + (size_t)(t * 32) * K);
                bv[t] = *(const float4*)(Bp + k0 + GK + (size_t)(t * 32) * K);
            }
        }

        const uint32_t* As = Asb + buf * GASZ;
        const uint32_t* Bs = Bsb + buf * GASZ;
#pragma unroll
        for (int ks = 0; ks < 4; ks++) {
            const int k = ks * 8;
            uint32_t af[4][4], bf[4][2];
#pragma unroll
            for (int im = 0; im < 4; im++) {
                const int mr = wm * 64 + im * 16 + gr;
                af[im][0] = As[mr * GPITCH + k + gc];
                af[im][1] = As[(mr + 8) * GPITCH + k + gc];
                af[im][2] = As[mr * GPITCH + k + gc + 4];
                af[im][3] = As[(mr + 8) * GPITCH + k + gc + 4];
            }
#pragma unroll
            for (int jn = 0; jn < 4; jn++) {
                const int nr = wn * 32 + jn * 8 + gr;
                bf[jn][0] = Bs[nr * GPITCH + k + gc];
                bf[jn][1] = Bs[nr * GPITCH + k + gc + 4];
            }
#pragma unroll
            for (int im = 0; im < 4; im++)
#pragma unroll
                for (int jn = 0; jn < 4; jn++)
                    mma_tf32(c[im][jn], af[im], bf[jn]);
        }

        if (next) {
            uint32_t* Asn = Asb + (buf ^ 1) * GASZ;
            uint32_t* Bsn = Bsb + (buf ^ 1) * GASZ;
#pragma unroll
            for (int t = 0; t < 4; t++) {
                uint32_t* ad = Asn + (lr + t * 32) * GPITCH + lc;
                ad[0] = f2tf32(av[t].x); ad[1] = f2tf32(av[t].y);
                ad[2] = f2tf32(av[t].z); ad[3] = f2tf32(av[t].w);
                uint32_t* bd = Bsn + (lr + t * 32) * GPITCH + lc;
                bd[0] = f2tf32(bv[t].x); bd[1] = f2tf32(bv[t].y);
                bd[2] = f2tf32(bv[t].z); bd[3] = f2tf32(bv[t].w);
            }
            __syncthreads();
            buf ^= 1;
        }
    }

#pragma unroll
    for (int im = 0; im < 4; im++) {
        const int row = m0 + wm * 64 + im * 16 + gr;
#pragma unroll
        for (int jn = 0; jn < 4; jn++) {
            const int col = n0 + wn * 32 + jn * 8 + gc * 2;
            float* p0 = C + (size_t)row * N + col;
            float* p1 = C + (size_t)(row + 8) * N + col;
            p0[0] = c[im][jn][0]; p0[1] = c[im][jn][1];
            p1[0] = c[im][jn][2]; p1[1] = c[im][jn][3];
        }
    }
}

// =====================================================================
// Kernel 2: per-head RMSNorm (q,k) + RoPE (LUT) + transpose to [b,h,s,d]
// =====================================================================
__global__ __launch_bounds__(512)
void qkv_post(const float* __restrict__ qkv, const float* __restrict__ lut,
              const float* __restrict__ qw, const float* __restrict__ kw,
              float* __restrict__ Q, float* __restrict__ K, float* __restrict__ V) {
    const int row  = blockIdx.x;
    const int h    = threadIdx.x >> 5;
    const int lane = threadIdx.x & 31;
    const int b = row / S_;
    const int s = row - b * S_;

    const float* base = qkv + (size_t)row * (3 * DIM_) + h * DH_;
    float q1 = base[lane],            q2 = base[lane + 32];
    float k1 = base[DIM_ + lane],     k2 = base[DIM_ + lane + 32];
    float v1 = base[2*DIM_ + lane],   v2 = base[2*DIM_ + lane + 32];

    float qs = q1*q1 + q2*q2;
    float ks = k1*k1 + k2*k2;
#pragma unroll
    for (int o = 16; o >= 1; o >>= 1) {
        qs += __shfl_xor_sync(0xffffffffu, qs, o);
        ks += __shfl_xor_sync(0xffffffffu, ks, o);
    }
    const float qn = rsqrtf(qs * (1.0f / DH_) + 1e-6f);
    const float kn = rsqrtf(ks * (1.0f / DH_) + 1e-6f);

    q1 *= qn * qw[lane]; q2 *= qn * qw[lane + 32];
    k1 *= kn * kw[lane]; k2 *= kn * kw[lane + 32];

    const float cf = lut[s * DH_ + lane];
    const float sf = lut[s * DH_ + 32 + lane];

    const float qo1 = q1 * cf - q2 * sf;
    const float qo2 = q2 * cf + q1 * sf;
    const float ko1 = k1 * cf - k2 * sf;
    const float ko2 = k2 * cf + k1 * sf;

    const size_t o = (((size_t)(b * H_ + h)) * S_ + s) * DH_ + lane;
    Q[o] = qo1; Q[o + 32] = qo2;
    K[o] = ko1; K[o + 32] = ko2;
    V[o] = v1;  V[o + 32] = v2;
}

// =====================================================================
// Kernel 3: tensor-core causal flash attention (tf32 MMA)
// BM=128, BN=64, 256 threads (8 warps), warp = 16 q rows.
// Double-buffered K/V; next tile's LDGs overlap the PV MMAs.
// smem: Ks[2][64][68], Vs[2][64][72], Qs[128][68] (Qs reused as P)
// =====================================================================
#define KP 68
#define VP 72
#define KSZ (64 * KP)
#define VSZ (64 * VP)
#define QSZ (128 * KP)

__global__ __launch_bounds__(256)
void flash_attn_tc(const float* __restrict__ Q, const float* __restrict__ K,
                   const float* __restrict__ V, float* __restrict__ Out) {
    extern __shared__ uint32_t smx[];
    uint32_t* Ksb = smx;                       // [2][64*KP]
    uint32_t* Vsb = smx + 2 * KSZ;             // [2][64*VP]
    uint32_t* Qs  = smx + 2 * KSZ + 2 * VSZ;   // [128*KP], later P per-warp

    const int tid  = threadIdx.x;
    const int w    = tid >> 5;    // 0..7
    const int lane = tid & 31;
    const int gr   = lane >> 2;   // 0..7
    const int gc   = lane & 3;    // 0..3
    const int qt   = blockIdx.x;
    const int bh   = blockIdx.y;
    const int q0   = qt * 128;

    const float* Qg = Q + ((size_t)bh * S_ + q0) * DH_;
    const float* Kg = K + (size_t)bh * S_ * DH_;
    const float* Vg = V + (size_t)bh * S_ * DH_;

    // Q loader: 128 rows, each thread 32 floats
    const int qlr = tid >> 1;            // 0..127
    const int qlc = (tid & 1) * 32;      // 0 / 32
    // K/V loader: 64 rows, each thread 16 floats
    const int klr = tid >> 2;            // 0..63
    const int klc = (tid & 3) * 16;      // 0,16,32,48

    // ---- load Q tile (scaled, tf32) + K/V tile 0 into buffer 0 ----
    {
        const float* src = Qg + (size_t)qlr * DH_ + qlc;
        uint32_t* dst = Qs + qlr * KP + qlc;
#pragma unroll
        for (int i = 0; i < 8; i++) {
            float4 v = *(const float4*)(src + i * 4);
            dst[i*4+0] = f2tf32(v.x * 0.125f);
            dst[i*4+1] = f2tf32(v.y * 0.125f);
            dst[i*4+2] = f2tf32(v.z * 0.125f);
            dst[i*4+3] = f2tf32(v.w * 0.125f);
        }
        const float* ksrc = Kg + (size_t)klr * DH_ + klc;
        const float* vsrc = Vg + (size_t)klr * DH_ + klc;
        uint32_t* kd = Ksb + klr * KP + klc;
        uint32_t* vd = Vsb + klr * VP + klc;
#pragma unroll
        for (int i = 0; i < 4; i++) {
            float4 kv = *(const float4*)(ksrc + i * 4);
            float4 vv = *(const float4*)(vsrc + i * 4);
            kd[i*4+0] = f2tf32(kv.x); kd[i*4+1] = f2tf32(kv.y);
            kd[i*4+2] = f2tf32(kv.z); kd[i*4+3] = f2tf32(kv.w);
            vd[i*4+0] = f2tf32(vv.x); vd[i*4+1] = f2tf32(vv.y);
            vd[i*4+2] = f2tf32(vv.z); vd[i*4+3] = f2tf32(vv.w);
        }
    }
    __syncthreads();

    // ---- cache Q A-fragments in registers (whole KV loop) ----
    uint32_t qf[8][4];
    {
        const int m0r = (w * 16 + gr) * KP;
        const int m1r = (w * 16 + gr + 8) * KP;
#pragma unroll
        for (int ks = 0; ks < 8; ks++) {
            const int d0 = ks * 8 + gc;
            qf[ks][0] = Qs[m0r + d0];
            qf[ks][1] = Qs[m1r + d0];
            qf[ks][2] = Qs[m0r + d0 + 4];
            qf[ks][3] = Qs[m1r + d0 + 4];
        }
    }
    // per-warp P region reuses this warp's own 16 Q rows
    uint32_t* Ps = Qs + w * 16 * KP;

    float of[8][4];
#pragma unroll
    for (int j = 0; j < 8; j++)
#pragma unroll
        for (int e = 0; e < 4; e++) of[j][e] = 0.f;
    float m0 = -1e30f, m1 = -1e30f, l0 = 0.f, l1 = 0.f;

    const int nkt = 2 * qt + 2;          // 64-wide K tiles
    int buf = 0;
    for (int kt = 0; kt < nkt; kt++) {
        const uint32_t* Ks = Ksb + buf * KSZ;
        const uint32_t* Vs = Vsb + buf * VSZ;

        // ---- S = Q K^T  (per warp: 16 x 64) ----
        float sacc[8][4];
#pragma unroll
        for (int j = 0; j < 8; j++)
#pragma unroll
            for (int e = 0; e < 4; e++) sacc[j][e] = 0.f;

#pragma unroll
        for (int ks = 0; ks < 8; ks++) {
            const int d0 = ks * 8 + gc;
            uint32_t kb[8][2];
#pragma unroll
            for (int j = 0; j < 8; j++) {
                const int tr = (j * 8 + gr) * KP;
                kb[j][0] = Ks[tr + d0];
                kb[j][1] = Ks[tr + d0 + 4];
            }
#pragma unroll
            for (int j = 0; j < 8; j++) mma_tf32(sacc[j], qf[ks], kb[j]);
        }

        // ---- causal mask (only tiles crossing the diagonal) ----
        if (kt >= 2 * qt) {
            const int rg0 = q0 + w * 16 + gr, rg1 = rg0 + 8;
            const int cb  = kt * 64;
#pragma unroll
            for (int j = 0; j < 8; j++) {
                const int cg = cb + j * 8 + 2 * gc;
                if (cg     > rg0) sacc[j][0] = -1e30f;
                if (cg + 1 > rg0) sacc[j][1] = -1e30f;
                if (cg     > rg1) sacc[j][2] = -1e30f;
                if (cg + 1 > rg1) sacc[j][3] = -1e30f;
            }
        }

        // ---- online softmax ----
        float mx0 = -1e30f, mx1 = -1e30f;
#pragma unroll
        for (int j = 0; j < 8; j++) {
            mx0 = fmaxf(mx0, fmaxf(sacc[j][0], sacc[j][1]));
            mx1 = fmaxf(mx1, fmaxf(sacc[j][2], sacc[j][3]));
        }
        mx0 = fmaxf(mx0, __shfl_xor_sync(0xffffffffu, mx0, 1));
        mx0 = fmaxf(mx0, __shfl_xor_sync(0xffffffffu, mx0, 2));
        mx1 = fmaxf(mx1, __shfl_xor_sync(0xffffffffu, mx1, 1));
        mx1 = fmaxf(mx1, __shfl_xor_sync(0xffffffffu, mx1, 2));

        const float mn0 = fmaxf(m0, mx0);
        const float mn1 = fmaxf(m1, mx1);
        const float a0 = __expf(m0 - mn0);
        const float a1 = __expf(m1 - mn1);
        m0 = mn0; m1 = mn1;

        float rs0 = 0.f, rs1 = 0.f;
#pragma unroll
        for (int j = 0; j < 8; j++) {
            sacc[j][0] = __expf(sacc[j][0] - mn0);
            sacc[j][1] = __expf(sacc[j][1] - mn0);
            sacc[j][2] = __expf(sacc[j][2] - mn1);
            sacc[j][3] = __expf(sacc[j][3] - mn1);
            rs0 += sacc[j][0] + sacc[j][1];
            rs1 += sacc[j][2] + sacc[j][3];
        }
        rs0 += __shfl_xor_sync(0xffffffffu, rs0, 1);
        rs0 += __shfl_xor_sync(0xffffffffu, rs0, 2);
        rs1 += __shfl_xor_sync(0xffffffffu, rs1, 1);
        rs1 += __shfl_xor_sync(0xffffffffu, rs1, 2);
        l0 = l0 * a0 + rs0;
        l1 = l1 * a1 + rs1;

#pragma unroll
        for (int j = 0; j < 8; j++) {
            of[j][0] *= a0; of[j][1] *= a0;
            of[j][2] *= a1; of[j][3] *= a1;
        }

        // ---- stash P (tf32) in per-warp smem slice ----
#pragma unroll
        for (int j = 0; j < 8; j++) {
            const int c0 = j * 8 + 2 * gc;
            Ps[gr * KP + c0]           = f2tf32(sacc[j][0]);
            Ps[gr * KP + c0 + 1]       = f2tf32(sacc[j][1]);
            Ps[(gr + 8) * KP + c0]     = f2tf32(sacc[j][2]);
            Ps[(gr + 8) * KP + c0 + 1] = f2tf32(sacc[j][3]);
        }
        __syncwarp();

        // ---- issue next K/V tile's loads (overlap with PV MMAs) ----
        const bool next = (kt + 1) < nkt;
        float4 kr[4], vr[4];
        if (next) {
            const float* ksrc = Kg + ((size_t)((kt + 1) * 64 + klr)) * DH_ + klc;
            const float* vsrc = Vg + ((size_t)((kt + 1) * 64 + klr)) * DH_ + klc;
#pragma unroll
            for (int i = 0; i < 4; i++) {
                kr[i] = *(const float4*)(ksrc + i * 4);
                vr[i] = *(const float4*)(vsrc + i * 4);
            }
        }

        // ---- O += P V ----
#pragma unroll
        for (int ks = 0; ks < 8; ks++) {
            const int t0 = ks * 8;
            uint32_t pf[4];
            pf[0] = Ps[gr * KP + t0 + gc];
            pf[1] = Ps[(gr + 8) * KP + t0 + gc];
            pf[2] = Ps[gr * KP + t0 + gc + 4];
            pf[3] = Ps[(gr + 8) * KP + t0 + gc + 4];
            uint32_t vb[8][2];
#pragma unroll
            for (int j = 0; j < 8; j++) {
                vb[j][0] = Vs[(t0 + gc) * VP + j * 8 + gr];
                vb[j][1] = Vs[(t0 + gc + 4) * VP + j * 8 + gr];
            }
#pragma unroll
            for (int j = 0; j < 8; j++) mma_tf32(of[j], pf, vb[j]);
        }
        __syncwarp();

        // ---- store prefetched tile into other buffer, single sync ----
        if (next) {
            uint32_t* kd = Ksb + (buf ^ 1) * KSZ + klr * KP + klc;
            uint32_t* vd = Vsb + (buf ^ 1) * VSZ + klr * VP + klc;
#pragma unroll
            for (int i = 0; i < 4; i++) {
                kd[i*4+0] = f2tf32(kr[i].x); kd[i*4+1] = f2tf32(kr[i].y);
                kd[i*4+2] = f2tf32(kr[i].z); kd[i*4+3] = f2tf32(kr[i].w);
                vd[i*4+0] = f2tf32(vr[i].x); vd[i*4+1] = f2tf32(vr[i].y);
                vd[i*4+2] = f2tf32(vr[i].z); vd[i*4+3] = f2tf32(vr[i].w);
            }
            __syncthreads();
            buf ^= 1;
        }
    }

    // ---- epilogue: O/l -> attn buffer [b, s, h*64+d] ----
    const int b = bh >> 4;
    const int h = bh & 15;
    const float inv0 = 1.0f / l0;
    const float inv1 = 1.0f / l1;
    const int s0 = q0 + w * 16 + gr;
    const int s1 = s0 + 8;
#pragma unroll
    for (int j = 0; j < 8; j++) {
        const int col = h * DH_ + j * 8 + 2 * gc;
        float* p0 = Out + ((size_t)(b * S_ + s0)) * DIM_ + col;
        float* p1 = Out + ((size_t)(b * S_ + s1)) * DIM_ + col;
        *(float2*)p0 = make_float2(of[j][0] * inv0, of[j][1] * inv0);
        *(float2*)p1 = make_float2(of[j][2] * inv1, of[j][3] * inv1);
    }
}

// =====================================================================
extern "C" void kernel_launch(void* const* d_in, const int* in_sizes, int n_in,
                              void* d_out, int out_size) {
    const float* x     = (const float*)d_in[0];
    // d_in[1] = mask: causal tril(-1e9) — implemented structurally
    const float* rope  = (const float*)d_in[2];
    const float* w_qkv = (const float*)d_in[3];
    const float* w_out = (const float*)d_in[4];
    const float* qw    = (const float*)d_in[5];
    const float* kw    = (const float*)d_in[6];
    float* out = (float*)d_out;

    float *qkv_p, *q_p, *k_p, *v_p, *attn_p, *lut_p;
    cudaGetSymbolAddress((void**)&qkv_p,  g_qkv);
    cudaGetSymbolAddress((void**)&q_p,    g_q);
    cudaGetSymbolAddress((void**)&k_p,    g_k);
    cudaGetSymbolAddress((void**)&v_p,    g_v);
    cudaGetSymbolAddress((void**)&attn_p, g_attn);
    cudaGetSymbolAddress((void**)&lut_p,  g_rlut);

    const int gemm_smem = 4 * GASZ * sizeof(uint32_t);                     // 73728
    const int attn_smem = (2 * KSZ + 2 * VSZ + QSZ) * sizeof(uint32_t);    // 106496
    cudaFuncSetAttribute(gemm_tf32_nt, cudaFuncAttributeMaxDynamicSharedMemorySize, gemm_smem);
    cudaFuncSetAttribute(flash_attn_tc, cudaFuncAttributeMaxDynamicSharedMemorySize, attn_smem);

    const int M = B_ * S_;        // 4096

    // 0) RoPE LUT
    rope_lut<<<S_, 32>>>(rope, lut_p);

    // 1) QKV projection (tf32 tensor cores, pipelined)
    gemm_tf32_nt<<<dim3(3 * DIM_ / 128, M / 128), 256, gemm_smem>>>(x, w_qkv, qkv_p, M, 3 * DIM_, DIM_);

    // 2) RMSNorm + RoPE + transpose
    qkv_post<<<M, 512>>>(qkv_p, lut_p, qw, kw, q_p, k_p, v_p);

    // 3) causal flash attention (tf32 tensor cores, BM=128)
    flash_attn_tc<<<dim3(S_ / 128, B_ * H_), 256, attn_smem>>>(q_p, k_p, v_p, attn_p);

    // 4) output projection (tf32 tensor cores, pipelined)
    gemm_tf32_nt<<<dim3(DIM_ / 128, M / 128), 256, gemm_smem>>>(attn_p, w_out, out, M, DIM_, DIM_);
}